// round 6
// baseline (speedup 1.0000x reference)
#include <cuda_runtime.h>
#include <cuda_bf16.h>
#include <cstdint>

#define HID 1024
#define HEADS 8
#define DD 128
#define NSEG 16
#define SEGLEN 256
#define EE_N 16
#define II 512
#define NGROUP 512
#define MROWS 16384
#define SS_ 4096

__device__ __nv_bfloat16 g_xb_hi[MROWS * HID];
__device__ __nv_bfloat16 g_xb_lo[MROWS * HID];
__device__ __nv_bfloat16 g_wmh_hi[HID * HID];
__device__ __nv_bfloat16 g_wmh_lo[HID * HID];
__device__ __nv_bfloat16 g_wmg_hi[HID * HID];
__device__ __nv_bfloat16 g_wmg_lo[HID * HID];
__device__ __nv_bfloat16 g_xh_hi[MROWS * HID];
__device__ __nv_bfloat16 g_xh_lo[MROWS * HID];
__device__ float         g_ew[NGROUP * EE_N];
__device__ __nv_bfloat16 g_m1_hi[NGROUP * II * DD];
__device__ __nv_bfloat16 g_m1_lo[NGROUP * II * DD];
__device__ __nv_bfloat16 g_m2_hi[NGROUP * DD * II];
__device__ __nv_bfloat16 g_m2_lo[NGROUP * DD * II];
__device__ __nv_bfloat16 g_h_hi[NGROUP * SEGLEN * II];
__device__ __nv_bfloat16 g_h_lo[NGROUP * SEGLEN * II];
__device__ __nv_bfloat16 g_y2_hi[MROWS * HID];
__device__ __nv_bfloat16 g_y2_lo[MROWS * HID];

__device__ __forceinline__ uint32_t smem_u32(const void* p) {
    uint32_t a;
    asm("{ .reg .u64 t; cvta.to.shared.u64 t, %1; cvt.u32.u64 %0, t; }" : "=r"(a) : "l"(p));
    return a;
}
__device__ __forceinline__ void cp_async16(uint32_t dst, const void* src) {
    asm volatile("cp.async.cg.shared.global [%0], [%1], 16;" :: "r"(dst), "l"(src) : "memory");
}

#define LDSM4(r, ad) \
    asm volatile("ldmatrix.sync.aligned.m8n8.x4.shared.b16 {%0,%1,%2,%3}, [%4];" \
        : "=r"((r)[0]), "=r"((r)[1]), "=r"((r)[2]), "=r"((r)[3]) : "r"(ad))

#define MMA(c, a, b) \
    asm volatile("mma.sync.aligned.m16n8k16.row.col.f32.bf16.bf16.f32 " \
        "{%0,%1,%2,%3},{%4,%5,%6,%7},{%8,%9},{%0,%1,%2,%3};" \
        : "+f"((c)[0]), "+f"((c)[1]), "+f"((c)[2]), "+f"((c)[3]) \
        : "r"((a)[0]), "r"((a)[1]), "r"((a)[2]), "r"((a)[3]), "r"((b)[0]), "r"((b)[1]))

// SW64 swizzle: 64B rows, 8 ldmatrix rows hit 8 distinct 16B slots mod 128B
#define SWZ64(o) ((o) ^ ((((uint32_t)(o)) >> 3) & 0x30))

#define PLANE  8192
#define STAGE  (4 * PLANE)            // 32768
#define NSTAGE 3
#define SMEM_BYTES (NSTAGE * STAGE)   // 98304

#define COMMIT_EMPTY() asm volatile("cp.async.commit_group;" ::: "memory")

// C[128,128] += A * B^T over K (bf16 hi/lo planes, fp32 accum, 3 products)
__global__ __launch_bounds__(256)
void mma_gemm(const __nv_bfloat16* __restrict__ Ahi, const __nv_bfloat16* __restrict__ Alo,
              const __nv_bfloat16* __restrict__ Bhi, const __nv_bfloat16* __restrict__ Blo,
              __nv_bfloat16* __restrict__ Chi, __nv_bfloat16* __restrict__ Clo,
              float* __restrict__ Cf, const float* __restrict__ bias,
              int K, int lda, int ldb, int ldc,
              long long aB, long long bB, long long cB, int doRelu)
{
    extern __shared__ char dsm[];
    const int tid  = threadIdx.x;
    const int lane = tid & 31;
    const int warp = tid >> 5;
    const int wm   = warp & 1;
    const int wn   = warp >> 1;

    const long long gz = blockIdx.z;
    Ahi += gz * aB;  Alo += gz * aB;
    Bhi += gz * bB;  Blo += gz * bB;
    const long long coff = gz * cB;
    const int m0 = blockIdx.y * 128;
    const int n0 = blockIdx.x * 128;

    const uint32_t sb = smem_u32(dsm);
    const int NK = K >> 5;

    float acc[4][4][4];
#pragma unroll
    for (int i = 0; i < 4; i++)
#pragma unroll
        for (int j = 0; j < 4; j++)
#pragma unroll
            for (int q = 0; q < 4; q++) acc[i][j][q] = 0.f;

    // per-thread cp.async source/dest precompute: 8 chunks/stage
    const __nv_bfloat16* srcBase[8];
    uint32_t dstOff[8];
#pragma unroll
    for (int it = 0; it < 8; it++) {
        int idx = it * 256 + tid;
        int pl = idx >> 9;
        int r  = (idx >> 2) & 127;
        int ch = idx & 3;
        const __nv_bfloat16* sp;
        if (pl == 0)      sp = Ahi + (long long)(m0 + r) * lda + ch * 8;
        else if (pl == 1) sp = Alo + (long long)(m0 + r) * lda + ch * 8;
        else if (pl == 2) sp = Bhi + (long long)(n0 + r) * ldb + ch * 8;
        else              sp = Blo + (long long)(n0 + r) * ldb + ch * 8;
        srcBase[it] = sp;
        dstOff[it] = pl * PLANE + SWZ64(r * 64 + ch * 16);
    }

#define ISSUE(kt)                                                              \
    do {                                                                       \
        const int koff_ = (kt) << 5;                                           \
        const uint32_t db_ = sb + ((kt) % NSTAGE) * STAGE;                     \
        _Pragma("unroll")                                                      \
        for (int it = 0; it < 8; it++)                                         \
            cp_async16(db_ + dstOff[it], srcBase[it] + koff_);                 \
        asm volatile("cp.async.commit_group;" ::: "memory");                   \
    } while (0)

    const int rowOffA = (lane & 7) + ((lane >> 3) & 1) * 8;
    const int kOffA   = ((lane >> 4) & 1) * 8;
    const int rowOffB = (lane & 7) + ((lane >> 4) & 1) * 8;
    const int kOffB   = ((lane >> 3) & 1) * 8;

    ISSUE(0);
    if (NK > 1) { ISSUE(1); } else { COMMIT_EMPTY(); }

    for (int kt = 0; kt < NK; kt++) {
        asm volatile("cp.async.wait_group 1;" ::: "memory");
        __syncthreads();
        if (kt + 2 < NK) { ISSUE(kt + 2); } else { COMMIT_EMPTY(); }

        const uint32_t base = sb + (kt % NSTAGE) * STAGE;
#pragma unroll
        for (int ks = 0; ks < 2; ks++) {
            uint32_t a_h[4][4], a_l[4][4], b_h[4][2], b_l[4][2];
#pragma unroll
            for (int mt = 0; mt < 4; mt++) {
                uint32_t off = SWZ64((wm * 64 + mt * 16 + rowOffA) * 64
                                     + (ks * 16 + kOffA) * 2);
                LDSM4(a_h[mt], base + off);
                LDSM4(a_l[mt], base + PLANE + off);
            }
#pragma unroll
            for (int pr = 0; pr < 2; pr++) {
                uint32_t off = SWZ64((wn * 32 + pr * 16 + rowOffB) * 64
                                     + (ks * 16 + kOffB) * 2);
                uint32_t r4[4];
                LDSM4(r4, base + 2 * PLANE + off);
                b_h[pr * 2][0] = r4[0]; b_h[pr * 2][1] = r4[1];
                b_h[pr * 2 + 1][0] = r4[2]; b_h[pr * 2 + 1][1] = r4[3];
                LDSM4(r4, base + 3 * PLANE + off);
                b_l[pr * 2][0] = r4[0]; b_l[pr * 2][1] = r4[1];
                b_l[pr * 2 + 1][0] = r4[2]; b_l[pr * 2 + 1][1] = r4[3];
            }
#pragma unroll
            for (int mt = 0; mt < 4; mt++)
#pragma unroll
                for (int nt = 0; nt < 4; nt++) {
                    MMA(acc[mt][nt], a_h[mt], b_h[nt]);
                    MMA(acc[mt][nt], a_h[mt], b_l[nt]);
                    MMA(acc[mt][nt], a_l[mt], b_h[nt]);
                }
        }
        __syncthreads();
    }

    // epilogue
    const int rq = lane >> 2;
    const int cq = (lane & 3) * 2;
#pragma unroll
    for (int mt = 0; mt < 4; mt++)
#pragma unroll
        for (int nt = 0; nt < 4; nt++) {
            const int row = m0 + wm * 64 + mt * 16 + rq;
            const int col = n0 + wn * 32 + nt * 8 + cq;
            float b0 = bias ? bias[col] : 0.f;
            float b1 = bias ? bias[col + 1] : 0.f;
#pragma unroll
            for (int half = 0; half < 2; half++) {
                const long long rr = (long long)(row + half * 8) * ldc + col + coff;
                float v0 = acc[mt][nt][half * 2 + 0] + b0;
                float v1 = acc[mt][nt][half * 2 + 1] + b1;
                if (doRelu) { v0 = fmaxf(v0, 0.f); v1 = fmaxf(v1, 0.f); }
                if (Cf) {
                    *reinterpret_cast<float2*>(Cf + rr) = make_float2(v0, v1);
                } else {
                    __nv_bfloat16 h0 = __float2bfloat16(v0);
                    __nv_bfloat16 h1 = __float2bfloat16(v1);
                    __nv_bfloat162 hp; hp.x = h0; hp.y = h1;
                    __nv_bfloat162 lp;
                    lp.x = __float2bfloat16(v0 - __bfloat162float(h0));
                    lp.y = __float2bfloat16(v1 - __bfloat162float(h1));
                    *reinterpret_cast<__nv_bfloat162*>(Chi + rr) = hp;
                    *reinterpret_cast<__nv_bfloat162*>(Clo + rr) = lp;
                }
            }
        }
}

__global__ void split_kernel(const float4* __restrict__ in,
                             __nv_bfloat16* __restrict__ hi,
                             __nv_bfloat16* __restrict__ lo, int n4)
{
    for (long long i = blockIdx.x * blockDim.x + threadIdx.x; i < n4;
         i += (long long)gridDim.x * blockDim.x) {
        float4 v = in[i];
        __nv_bfloat162 a, b, c, d;
        a.x = __float2bfloat16(v.x); a.y = __float2bfloat16(v.y);
        b.x = __float2bfloat16(v.z); b.y = __float2bfloat16(v.w);
        c.x = __float2bfloat16(v.x - __bfloat162float(a.x));
        c.y = __float2bfloat16(v.y - __bfloat162float(a.y));
        d.x = __float2bfloat16(v.z - __bfloat162float(b.x));
        d.y = __float2bfloat16(v.w - __bfloat162float(b.y));
        reinterpret_cast<__nv_bfloat162*>(hi)[2 * i]     = a;
        reinterpret_cast<__nv_bfloat162*>(hi)[2 * i + 1] = b;
        reinterpret_cast<__nv_bfloat162*>(lo)[2 * i]     = c;
        reinterpret_cast<__nv_bfloat162*>(lo)[2 * i + 1] = d;
    }
}

__global__ void avg_softmax_kernel(const __nv_bfloat16* __restrict__ xhh,
                                   const __nv_bfloat16* __restrict__ xhl,
                                   const float* __restrict__ embed,
                                   float* __restrict__ ew)
{
    __shared__ float avg_s[DD];
    __shared__ float lg[EE_N];

    const int g = blockIdx.x;
    const int d = threadIdx.x;
    const int b = g >> 7;
    const int n = (g >> 3) & 15;
    const int h = g & 7;

    const long long base = (long long)(b * SS_ + n * SEGLEN) * HID + h * DD + d;
    float s = 0.f;
#pragma unroll 8
    for (int l = 0; l < SEGLEN; l++) {
        long long p = base + (long long)l * HID;
        s += __bfloat162float(xhh[p]) + __bfloat162float(xhl[p]);
    }
    avg_s[d] = s * (1.f / (float)SEGLEN);
    __syncthreads();

    if (d < EE_N) {
        float a = 0.f;
        for (int dd = 0; dd < DD; dd++) a += avg_s[dd] * embed[dd * EE_N + d];
        lg[d] = a;
    }
    __syncthreads();

    if (d == 0) {
        float mx = lg[0];
        for (int e = 1; e < EE_N; e++) mx = fmaxf(mx, lg[e]);
        float ex[EE_N], ssum = 0.f;
        for (int e = 0; e < EE_N; e++) { ex[e] = expf(lg[e] - mx); ssum += ex[e]; }
        float inv = 1.f / ssum;
        for (int e = 0; e < EE_N; e++) ew[g * EE_N + e] = ex[e] * inv;
    }
}

__global__ void mix_kernel(const float* __restrict__ ew,
                           const float* __restrict__ fl1,
                           const float* __restrict__ fl2,
                           __nv_bfloat16* __restrict__ m1h, __nv_bfloat16* __restrict__ m1l,
                           __nv_bfloat16* __restrict__ m2h, __nv_bfloat16* __restrict__ m2l)
{
    __shared__ float w_s[NGROUP * EE_N];
    const int t = threadIdx.x;
    const float* src = blockIdx.y ? fl2 : fl1;
    __nv_bfloat16* dh = blockIdx.y ? m2h : m1h;
    __nv_bfloat16* dl = blockIdx.y ? m2l : m1l;
    const long long p = (long long)blockIdx.x * 128 + t;

    for (int idx = t; idx < NGROUP * EE_N; idx += 128) {
        int g = idx >> 4;
        int n = (g >> 3) & 15;
        int gs = (n > 0) ? (g - HEADS) : g;
        w_s[idx] = ew[gs * EE_N + (idx & 15)];
    }
    float flr[EE_N];
#pragma unroll
    for (int e = 0; e < EE_N; e++) flr[e] = src[(long long)e * (II * DD) + p];
    __syncthreads();

    for (int g = 0; g < NGROUP; g++) {
        float acc = 0.f;
#pragma unroll
        for (int e = 0; e < EE_N; e++) acc = fmaf(w_s[g * EE_N + e], flr[e], acc);
        __nv_bfloat16 h = __float2bfloat16(acc);
        dh[(long long)g * (II * DD) + p] = h;
        dl[(long long)g * (II * DD) + p] = __float2bfloat16(acc - __bfloat162float(h));
    }
}

extern "C" void kernel_launch(void* const* d_in, const int* in_sizes, int n_in,
                              void* d_out, int out_size)
{
    const float* x       = (const float*)d_in[0];
    const float* W_mh    = (const float*)d_in[1];
    const float* b_mh    = (const float*)d_in[2];
    const float* W_merge = (const float*)d_in[3];
    const float* b_merge = (const float*)d_in[4];
    const float* embed   = (const float*)d_in[5];
    const float* fl1     = (const float*)d_in[6];
    const float* fl2     = (const float*)d_in[7];
    float* out = (float*)d_out;

    __nv_bfloat16 *xbh, *xbl, *wmhh, *wmhl, *wmgh, *wmgl, *xhh, *xhl;
    __nv_bfloat16 *m1h, *m1l, *m2h, *m2l, *hh, *hl, *y2h, *y2l;
    float* ew;
    cudaGetSymbolAddress((void**)&xbh, g_xb_hi);   cudaGetSymbolAddress((void**)&xbl, g_xb_lo);
    cudaGetSymbolAddress((void**)&wmhh, g_wmh_hi); cudaGetSymbolAddress((void**)&wmhl, g_wmh_lo);
    cudaGetSymbolAddress((void**)&wmgh, g_wmg_hi); cudaGetSymbolAddress((void**)&wmgl, g_wmg_lo);
    cudaGetSymbolAddress((void**)&xhh, g_xh_hi);   cudaGetSymbolAddress((void**)&xhl, g_xh_lo);
    cudaGetSymbolAddress((void**)&m1h, g_m1_hi);   cudaGetSymbolAddress((void**)&m1l, g_m1_lo);
    cudaGetSymbolAddress((void**)&m2h, g_m2_hi);   cudaGetSymbolAddress((void**)&m2l, g_m2_lo);
    cudaGetSymbolAddress((void**)&hh, g_h_hi);     cudaGetSymbolAddress((void**)&hl, g_h_lo);
    cudaGetSymbolAddress((void**)&y2h, g_y2_hi);   cudaGetSymbolAddress((void**)&y2l, g_y2_lo);
    cudaGetSymbolAddress((void**)&ew, g_ew);

    cudaFuncSetAttribute(mma_gemm, cudaFuncAttributeMaxDynamicSharedMemorySize, SMEM_BYTES);

    split_kernel<<<2048, 256>>>((const float4*)x, xbh, xbl, MROWS * HID / 4);
    split_kernel<<<256, 256>>>((const float4*)W_mh, wmhh, wmhl, HID * HID / 4);
    split_kernel<<<256, 256>>>((const float4*)W_merge, wmgh, wmgl, HID * HID / 4);

    mma_gemm<<<dim3(HID / 128, MROWS / 128, 1), 256, SMEM_BYTES>>>(
        xbh, xbl, wmhh, wmhl, xhh, xhl, nullptr, b_mh,
        HID, HID, HID, HID, 0, 0, 0, 0);

    avg_softmax_kernel<<<NGROUP, DD>>>(xhh, xhl, embed, ew);

    mix_kernel<<<dim3(II * DD / 128, 2), 128>>>(ew, fl1, fl2, m1h, m1l, m2h, m2l);

    mma_gemm<<<dim3(II / 128, SEGLEN / 128, NGROUP), 256, SMEM_BYTES>>>(
        xhh, xhl, m1h, m1l, hh, hl, nullptr, nullptr,
        DD, DD, DD, II,
        (long long)SEGLEN * DD, (long long)II * DD, (long long)SEGLEN * II, 1);

    mma_gemm<<<dim3(DD / 128, SEGLEN / 128, NGROUP), 256, SMEM_BYTES>>>(
        hh, hl, m2h, m2l, y2h, y2l, nullptr, nullptr,
        II, II, II, DD,
        (long long)SEGLEN * II, (long long)DD * II, (long long)SEGLEN * DD, 0);

    mma_gemm<<<dim3(HID / 128, MROWS / 128, 1), 256, SMEM_BYTES>>>(
        y2h, y2l, wmgh, wmgl, nullptr, nullptr, out, b_merge,
        HID, HID, HID, HID, 0, 0, 0, 0);
}

// round 8
// speedup vs baseline: 1.0103x; 1.0103x over previous
#include <cuda_runtime.h>
#include <cuda_bf16.h>
#include <cstdint>

#define HID 1024
#define HEADS 8
#define DD 128
#define NSEG 16
#define SEGLEN 256
#define EE_N 16
#define II 512
#define NGROUP 512
#define MROWS 16384
#define SS_ 4096

__device__ __nv_bfloat16 g_xb_hi[MROWS * HID];
__device__ __nv_bfloat16 g_xb_lo[MROWS * HID];
__device__ __nv_bfloat16 g_wmh_hi[HID * HID];
__device__ __nv_bfloat16 g_wmh_lo[HID * HID];
__device__ __nv_bfloat16 g_wmg_hi[HID * HID];
__device__ __nv_bfloat16 g_wmg_lo[HID * HID];
__device__ __nv_bfloat16 g_xh_hi[MROWS * HID];
__device__ __nv_bfloat16 g_xh_lo[MROWS * HID];
__device__ float         g_ew[NGROUP * EE_N];
__device__ __nv_bfloat16 g_m1_hi[NGROUP * II * DD];
__device__ __nv_bfloat16 g_m1_lo[NGROUP * II * DD];
__device__ __nv_bfloat16 g_m2_hi[NGROUP * DD * II];
__device__ __nv_bfloat16 g_m2_lo[NGROUP * DD * II];
__device__ __nv_bfloat16 g_h_hi[NGROUP * SEGLEN * II];
__device__ __nv_bfloat16 g_h_lo[NGROUP * SEGLEN * II];
__device__ __nv_bfloat16 g_y2_hi[MROWS * HID];
__device__ __nv_bfloat16 g_y2_lo[MROWS * HID];

__device__ __forceinline__ uint32_t smem_u32(const void* p) {
    uint32_t a;
    asm("{ .reg .u64 t; cvta.to.shared.u64 t, %1; cvt.u32.u64 %0, t; }" : "=r"(a) : "l"(p));
    return a;
}
__device__ __forceinline__ void cp_async16(uint32_t dst, const void* src) {
    asm volatile("cp.async.cg.shared.global [%0], [%1], 16;" :: "r"(dst), "l"(src) : "memory");
}

#define LDSM4(r, ad) \
    asm volatile("ldmatrix.sync.aligned.m8n8.x4.shared.b16 {%0,%1,%2,%3}, [%4];" \
        : "=r"((r)[0]), "=r"((r)[1]), "=r"((r)[2]), "=r"((r)[3]) : "r"(ad))

#define MMA(c, a, b) \
    asm volatile("mma.sync.aligned.m16n8k16.row.col.f32.bf16.bf16.f32 " \
        "{%0,%1,%2,%3},{%4,%5,%6,%7},{%8,%9},{%0,%1,%2,%3};" \
        : "+f"((c)[0]), "+f"((c)[1]), "+f"((c)[2]), "+f"((c)[3]) \
        : "r"((a)[0]), "r"((a)[1]), "r"((a)[2]), "r"((a)[3]), "r"((b)[0]), "r"((b)[1]))

// pitch-80 rows: 8 consecutive rows hit 8 distinct 16B slots mod 128B (proven R4)
#define RPITCH 80
#define PLANE  (128 * RPITCH)         // 10240
#define STAGE  (4 * PLANE)            // 40960
#define SMEM_BYTES (2 * STAGE)        // 81920 (2 CTAs/SM, proven R4)

// C[128,128] += A * B^T over K; bf16 hi/lo planes; fp32 accum; 3 products.
// 4 warps, warp tile 64x64. K % 32 == 0.
__global__ __launch_bounds__(128)
void mma_gemm(const __nv_bfloat16* __restrict__ Ahi, const __nv_bfloat16* __restrict__ Alo,
              const __nv_bfloat16* __restrict__ Bhi, const __nv_bfloat16* __restrict__ Blo,
              __nv_bfloat16* __restrict__ Chi, __nv_bfloat16* __restrict__ Clo,
              float* __restrict__ Cf, const float* __restrict__ bias,
              int K, int lda, int ldb, int ldc,
              long long aB, long long bB, long long cB, int doRelu)
{
    extern __shared__ char dsm[];
    const int tid  = threadIdx.x;
    const int lane = tid & 31;
    const int warp = tid >> 5;
    const int wm   = warp & 1;        // 0..1 : 64-row slab
    const int wn   = warp >> 1;       // 0..1 : 64-col slab

    const long long gz = blockIdx.z;
    Ahi += gz * aB;  Alo += gz * aB;
    Bhi += gz * bB;  Blo += gz * bB;
    const long long coff = gz * cB;
    const int m0 = blockIdx.y * 128;
    const int n0 = blockIdx.x * 128;

    const uint32_t sb = smem_u32(dsm);
    const int NK = K >> 5;

    float acc[4][8][4];
#pragma unroll
    for (int i = 0; i < 4; i++)
#pragma unroll
        for (int j = 0; j < 8; j++)
#pragma unroll
            for (int q = 0; q < 4; q++) acc[i][j][q] = 0.f;

    // cp.async addressing: per plane one base; rows r0 + it*32 (it 0..3), 16B chunk ch
    const int r0 = tid >> 2;          // 0..31
    const int ch = tid & 3;           // 0..3
    const __nv_bfloat16* srcB[4];
    srcB[0] = Ahi + (long long)(m0 + r0) * lda + ch * 8;
    srcB[1] = Alo + (long long)(m0 + r0) * lda + ch * 8;
    srcB[2] = Bhi + (long long)(n0 + r0) * ldb + ch * 8;
    srcB[3] = Blo + (long long)(n0 + r0) * ldb + ch * 8;
    long long rstep[4];
    rstep[0] = rstep[1] = 32LL * lda;
    rstep[2] = rstep[3] = 32LL * ldb;
    const uint32_t dstB = r0 * RPITCH + ch * 16;

#define ISSUE(kt)                                                              \
    do {                                                                       \
        const int koff_ = (kt) << 5;                                           \
        const uint32_t db_ = sb + ((kt) & 1) * STAGE + dstB;                   \
        _Pragma("unroll")                                                      \
        for (int pl = 0; pl < 4; pl++)                                         \
            _Pragma("unroll")                                                  \
            for (int it = 0; it < 4; it++)                                     \
                cp_async16(db_ + pl * PLANE + it * (32 * RPITCH),              \
                           srcB[pl] + koff_ + it * rstep[pl]);                 \
        asm volatile("cp.async.commit_group;" ::: "memory");                   \
    } while (0)

    const int rowOffA = (lane & 7) + ((lane >> 3) & 1) * 8;
    const int kOffA   = ((lane >> 4) & 1) * 8;
    const int rowOffB = (lane & 7) + ((lane >> 4) & 1) * 8;
    const int kOffB   = ((lane >> 3) & 1) * 8;

    ISSUE(0);
    for (int kt = 0; kt < NK; kt++) {
        if (kt + 1 < NK) {
            ISSUE(kt + 1);
            asm volatile("cp.async.wait_group 1;" ::: "memory");
        } else {
            asm volatile("cp.async.wait_group 0;" ::: "memory");
        }
        __syncthreads();

        const uint32_t base = sb + (kt & 1) * STAGE;
#pragma unroll
        for (int ks = 0; ks < 2; ks++) {
            uint32_t a_h[4][4], a_l[4][4];
#pragma unroll
            for (int mt = 0; mt < 4; mt++) {
                uint32_t ad = base + (wm * 64 + mt * 16 + rowOffA) * RPITCH
                            + (ks * 16 + kOffA) * 2;
                LDSM4(a_h[mt], ad);
                LDSM4(a_l[mt], ad + PLANE);
            }
#pragma unroll
            for (int h2 = 0; h2 < 2; h2++) {
                uint32_t b_h[4][2], b_l[4][2];
#pragma unroll
                for (int pr = 0; pr < 2; pr++) {
                    uint32_t bd = base + 2 * PLANE
                                + (wn * 64 + h2 * 32 + pr * 16 + rowOffB) * RPITCH
                                + (ks * 16 + kOffB) * 2;
                    uint32_t r4[4];
                    LDSM4(r4, bd);
                    b_h[pr * 2][0] = r4[0]; b_h[pr * 2][1] = r4[1];
                    b_h[pr * 2 + 1][0] = r4[2]; b_h[pr * 2 + 1][1] = r4[3];
                    LDSM4(r4, bd + PLANE);
                    b_l[pr * 2][0] = r4[0]; b_l[pr * 2][1] = r4[1];
                    b_l[pr * 2 + 1][0] = r4[2]; b_l[pr * 2 + 1][1] = r4[3];
                }
#pragma unroll
                for (int mt = 0; mt < 4; mt++)
#pragma unroll
                    for (int nt = 0; nt < 4; nt++) {
                        MMA(acc[mt][h2 * 4 + nt], a_h[mt], b_h[nt]);
                        MMA(acc[mt][h2 * 4 + nt], a_h[mt], b_l[nt]);
                        MMA(acc[mt][h2 * 4 + nt], a_l[mt], b_h[nt]);
                    }
            }
        }
        __syncthreads();
    }

    // epilogue: warp covers rows wm*64..+63, cols wn*64..+63
    const int rq = lane >> 2;
    const int cq = (lane & 3) * 2;
#pragma unroll
    for (int mt = 0; mt < 4; mt++)
#pragma unroll
        for (int nt = 0; nt < 8; nt++) {
            const int row = m0 + wm * 64 + mt * 16 + rq;
            const int col = n0 + wn * 64 + nt * 8 + cq;
            float b0 = bias ? bias[col] : 0.f;
            float b1 = bias ? bias[col + 1] : 0.f;
#pragma unroll
            for (int half = 0; half < 2; half++) {
                const long long rr = (long long)(row + half * 8) * ldc + col + coff;
                float v0 = acc[mt][nt][half * 2 + 0] + b0;
                float v1 = acc[mt][nt][half * 2 + 1] + b1;
                if (doRelu) { v0 = fmaxf(v0, 0.f); v1 = fmaxf(v1, 0.f); }
                if (Cf) {
                    *reinterpret_cast<float2*>(Cf + rr) = make_float2(v0, v1);
                } else {
                    __nv_bfloat16 h0 = __float2bfloat16(v0);
                    __nv_bfloat16 h1 = __float2bfloat16(v1);
                    __nv_bfloat162 hp; hp.x = h0; hp.y = h1;
                    __nv_bfloat162 lp;
                    lp.x = __float2bfloat16(v0 - __bfloat162float(h0));
                    lp.y = __float2bfloat16(v1 - __bfloat162float(h1));
                    *reinterpret_cast<__nv_bfloat162*>(Chi + rr) = hp;
                    *reinterpret_cast<__nv_bfloat162*>(Clo + rr) = lp;
                }
            }
        }
}

__global__ void split_kernel(const float4* __restrict__ in,
                             __nv_bfloat16* __restrict__ hi,
                             __nv_bfloat16* __restrict__ lo, int n4)
{
    for (long long i = blockIdx.x * blockDim.x + threadIdx.x; i < n4;
         i += (long long)gridDim.x * blockDim.x) {
        float4 v = in[i];
        __nv_bfloat162 a, b, c, d;
        a.x = __float2bfloat16(v.x); a.y = __float2bfloat16(v.y);
        b.x = __float2bfloat16(v.z); b.y = __float2bfloat16(v.w);
        c.x = __float2bfloat16(v.x - __bfloat162float(a.x));
        c.y = __float2bfloat16(v.y - __bfloat162float(a.y));
        d.x = __float2bfloat16(v.z - __bfloat162float(b.x));
        d.y = __float2bfloat16(v.w - __bfloat162float(b.y));
        reinterpret_cast<__nv_bfloat162*>(hi)[2 * i]     = a;
        reinterpret_cast<__nv_bfloat162*>(hi)[2 * i + 1] = b;
        reinterpret_cast<__nv_bfloat162*>(lo)[2 * i]     = c;
        reinterpret_cast<__nv_bfloat162*>(lo)[2 * i + 1] = d;
    }
}

__global__ void avg_softmax_kernel(const __nv_bfloat16* __restrict__ xhh,
                                   const __nv_bfloat16* __restrict__ xhl,
                                   const float* __restrict__ embed,
                                   float* __restrict__ ew)
{
    __shared__ float avg_s[DD];
    __shared__ float lg[EE_N];

    const int g = blockIdx.x;
    const int d = threadIdx.x;
    const int b = g >> 7;
    const int n = (g >> 3) & 15;
    const int h = g & 7;

    const long long base = (long long)(b * SS_ + n * SEGLEN) * HID + h * DD + d;
    float s = 0.f;
#pragma unroll 8
    for (int l = 0; l < SEGLEN; l++) {
        long long p = base + (long long)l * HID;
        s += __bfloat162float(xhh[p]) + __bfloat162float(xhl[p]);
    }
    avg_s[d] = s * (1.f / (float)SEGLEN);
    __syncthreads();

    if (d < EE_N) {
        float a = 0.f;
        for (int dd = 0; dd < DD; dd++) a += avg_s[dd] * embed[dd * EE_N + d];
        lg[d] = a;
    }
    __syncthreads();

    if (d == 0) {
        float mx = lg[0];
        for (int e = 1; e < EE_N; e++) mx = fmaxf(mx, lg[e]);
        float ex[EE_N], ssum = 0.f;
        for (int e = 0; e < EE_N; e++) { ex[e] = expf(lg[e] - mx); ssum += ex[e]; }
        float inv = 1.f / ssum;
        for (int e = 0; e < EE_N; e++) ew[g * EE_N + e] = ex[e] * inv;
    }
}

__global__ void mix_kernel(const float* __restrict__ ew,
                           const float* __restrict__ fl1,
                           const float* __restrict__ fl2,
                           __nv_bfloat16* __restrict__ m1h, __nv_bfloat16* __restrict__ m1l,
                           __nv_bfloat16* __restrict__ m2h, __nv_bfloat16* __restrict__ m2l)
{
    __shared__ float w_s[NGROUP * EE_N];
    const int t = threadIdx.x;
    const float* src = blockIdx.y ? fl2 : fl1;
    __nv_bfloat16* dh = blockIdx.y ? m2h : m1h;
    __nv_bfloat16* dl = blockIdx.y ? m2l : m1l;
    const long long p = (long long)blockIdx.x * 128 + t;

    for (int idx = t; idx < NGROUP * EE_N; idx += 128) {
        int g = idx >> 4;
        int n = (g >> 3) & 15;
        int gs = (n > 0) ? (g - HEADS) : g;
        w_s[idx] = ew[gs * EE_N + (idx & 15)];
    }
    float flr[EE_N];
#pragma unroll
    for (int e = 0; e < EE_N; e++) flr[e] = src[(long long)e * (II * DD) + p];
    __syncthreads();

    for (int g = 0; g < NGROUP; g++) {
        float acc = 0.f;
#pragma unroll
        for (int e = 0; e < EE_N; e++) acc = fmaf(w_s[g * EE_N + e], flr[e], acc);
        __nv_bfloat16 h = __float2bfloat16(acc);
        dh[(long long)g * (II * DD) + p] = h;
        dl[(long long)g * (II * DD) + p] = __float2bfloat16(acc - __bfloat162float(h));
    }
}

extern "C" void kernel_launch(void* const* d_in, const int* in_sizes, int n_in,
                              void* d_out, int out_size)
{
    const float* x       = (const float*)d_in[0];
    const float* W_mh    = (const float*)d_in[1];
    const float* b_mh    = (const float*)d_in[2];
    const float* W_merge = (const float*)d_in[3];
    const float* b_merge = (const float*)d_in[4];
    const float* embed   = (const float*)d_in[5];
    const float* fl1     = (const float*)d_in[6];
    const float* fl2     = (const float*)d_in[7];
    float* out = (float*)d_out;

    __nv_bfloat16 *xbh, *xbl, *wmhh, *wmhl, *wmgh, *wmgl, *xhh, *xhl;
    __nv_bfloat16 *m1h, *m1l, *m2h, *m2l, *hh, *hl, *y2h, *y2l;
    float* ew;
    cudaGetSymbolAddress((void**)&xbh, g_xb_hi);   cudaGetSymbolAddress((void**)&xbl, g_xb_lo);
    cudaGetSymbolAddress((void**)&wmhh, g_wmh_hi); cudaGetSymbolAddress((void**)&wmhl, g_wmh_lo);
    cudaGetSymbolAddress((void**)&wmgh, g_wmg_hi); cudaGetSymbolAddress((void**)&wmgl, g_wmg_lo);
    cudaGetSymbolAddress((void**)&xhh, g_xh_hi);   cudaGetSymbolAddress((void**)&xhl, g_xh_lo);
    cudaGetSymbolAddress((void**)&m1h, g_m1_hi);   cudaGetSymbolAddress((void**)&m1l, g_m1_lo);
    cudaGetSymbolAddress((void**)&m2h, g_m2_hi);   cudaGetSymbolAddress((void**)&m2l, g_m2_lo);
    cudaGetSymbolAddress((void**)&hh, g_h_hi);     cudaGetSymbolAddress((void**)&hl, g_h_lo);
    cudaGetSymbolAddress((void**)&y2h, g_y2_hi);   cudaGetSymbolAddress((void**)&y2l, g_y2_lo);
    cudaGetSymbolAddress((void**)&ew, g_ew);

    cudaFuncSetAttribute(mma_gemm, cudaFuncAttributeMaxDynamicSharedMemorySize, SMEM_BYTES);

    split_kernel<<<2048, 256>>>((const float4*)x, xbh, xbl, MROWS * HID / 4);
    split_kernel<<<256, 256>>>((const float4*)W_mh, wmhh, wmhl, HID * HID / 4);
    split_kernel<<<256, 256>>>((const float4*)W_merge, wmgh, wmgl, HID * HID / 4);

    mma_gemm<<<dim3(HID / 128, MROWS / 128, 1), 128, SMEM_BYTES>>>(
        xbh, xbl, wmhh, wmhl, xhh, xhl, nullptr, b_mh,
        HID, HID, HID, HID, 0, 0, 0, 0);

    avg_softmax_kernel<<<NGROUP, DD>>>(xhh, xhl, embed, ew);

    mix_kernel<<<dim3(II * DD / 128, 2), 128>>>(ew, fl1, fl2, m1h, m1l, m2h, m2l);

    mma_gemm<<<dim3(II / 128, SEGLEN / 128, NGROUP), 128, SMEM_BYTES>>>(
        xhh, xhl, m1h, m1l, hh, hl, nullptr, nullptr,
        DD, DD, DD, II,
        (long long)SEGLEN * DD, (long long)II * DD, (long long)SEGLEN * II, 1);

    mma_gemm<<<dim3(DD / 128, SEGLEN / 128, NGROUP), 128, SMEM_BYTES>>>(
        hh, hl, m2h, m2l, y2h, y2l, nullptr, nullptr,
        II, II, II, DD,
        (long long)SEGLEN * II, (long long)DD * II, (long long)SEGLEN * DD, 0);

    mma_gemm<<<dim3(HID / 128, MROWS / 128, 1), 128, SMEM_BYTES>>>(
        y2h, y2l, wmgh, wmgl, nullptr, nullptr, out, b_merge,
        HID, HID, HID, HID, 0, 0, 0, 0);
}

// round 9
// speedup vs baseline: 2.2090x; 2.1866x over previous
#include <cuda_runtime.h>
#include <cuda_fp16.h>
#include <cstdint>

#define HID 1024
#define HEADS 8
#define DD 128
#define NSEG 16
#define SEGLEN 256
#define EE_N 16
#define II 512
#define NGROUP 512
#define MROWS 16384
#define SS_ 4096

__device__ __half g_xb[MROWS * HID];
__device__ __half g_wmh[HID * HID];
__device__ __half g_wmg[HID * HID];
__device__ __half g_xh[MROWS * HID];
__device__ float  g_ew[NGROUP * EE_N];
__device__ __half g_m1[NGROUP * II * DD];
__device__ __half g_m2[NGROUP * DD * II];
__device__ __half g_h[NGROUP * SEGLEN * II];
__device__ __half g_y2[MROWS * HID];

__device__ __forceinline__ uint32_t smem_u32(const void* p) {
    uint32_t a;
    asm("{ .reg .u64 t; cvta.to.shared.u64 t, %1; cvt.u32.u64 %0, t; }" : "=r"(a) : "l"(p));
    return a;
}
__device__ __forceinline__ void cp_async16(uint32_t dst, const void* src) {
    asm volatile("cp.async.cg.shared.global [%0], [%1], 16;" :: "r"(dst), "l"(src) : "memory");
}

#define LDSM4(r, ad) \
    asm volatile("ldmatrix.sync.aligned.m8n8.x4.shared.b16 {%0,%1,%2,%3}, [%4];" \
        : "=r"((r)[0]), "=r"((r)[1]), "=r"((r)[2]), "=r"((r)[3]) : "r"(ad))

#define MMA(c, a, b) \
    asm volatile("mma.sync.aligned.m16n8k16.row.col.f32.f16.f16.f32 " \
        "{%0,%1,%2,%3},{%4,%5,%6,%7},{%8,%9},{%0,%1,%2,%3};" \
        : "+f"((c)[0]), "+f"((c)[1]), "+f"((c)[2]), "+f"((c)[3]) \
        : "r"((a)[0]), "r"((a)[1]), "r"((a)[2]), "r"((a)[3]), "r"((b)[0]), "r"((b)[1]))

// pitch-80 rows: 8 consecutive rows hit 8 distinct 16B slots mod 128B (proven R4)
#define RPITCH 80
#define PLANE  (128 * RPITCH)          // 10240
#define STAGE  (2 * PLANE)             // 20480 (A plane + B plane)
#define NSTAGE 3
#define SMEM_BYTES (NSTAGE * STAGE)    // 61440 -> 2 CTAs/SM

#define COMMIT_EMPTY() asm volatile("cp.async.commit_group;" ::: "memory")

// C[128,128] += A * B^T over K; fp16 operands; fp32 accum.
// 8 warps, warp tile 64x32 (proven R4 layout). K % 32 == 0.
__global__ __launch_bounds__(256)
void mma_gemm(const __half* __restrict__ A, const __half* __restrict__ B,
              __half* __restrict__ Ch, float* __restrict__ Cf,
              const float* __restrict__ bias,
              int K, int lda, int ldb, int ldc,
              long long aB, long long bB, long long cB, int doRelu)
{
    extern __shared__ char dsm[];
    const int tid  = threadIdx.x;
    const int lane = tid & 31;
    const int warp = tid >> 5;
    const int wm   = warp & 1;        // 0..1 : 64-row slab
    const int wn   = warp >> 1;       // 0..3 : 32-col slab

    const long long gz = blockIdx.z;
    A += gz * aB;
    B += gz * bB;
    const long long coff = gz * cB;
    const int m0 = blockIdx.y * 128;
    const int n0 = blockIdx.x * 128;

    const uint32_t sb = smem_u32(dsm);
    const int NK = K >> 5;

    float acc[4][4][4];
#pragma unroll
    for (int i = 0; i < 4; i++)
#pragma unroll
        for (int j = 0; j < 4; j++)
#pragma unroll
            for (int q = 0; q < 4; q++) acc[i][j][q] = 0.f;

    // cp.async: 2 planes x 128 rows x 4 chunks = 1024 chunks; 4 per thread
    const __half* srcP[4];
    uint32_t dstOff[4];
#pragma unroll
    for (int it = 0; it < 4; it++) {
        int idx = it * 256 + tid;
        int pl = idx >> 9;             // 0=A, 1=B
        int r  = (idx >> 2) & 127;
        int ch = idx & 3;
        srcP[it] = (pl ? B + (long long)(n0 + r) * ldb
                       : A + (long long)(m0 + r) * lda) + ch * 8;
        dstOff[it] = pl * PLANE + r * RPITCH + ch * 16;
    }

#define ISSUE(kt)                                                              \
    do {                                                                       \
        const int koff_ = (kt) << 5;                                           \
        const uint32_t db_ = sb + ((kt) % NSTAGE) * STAGE;                     \
        _Pragma("unroll")                                                      \
        for (int it = 0; it < 4; it++)                                         \
            cp_async16(db_ + dstOff[it], srcP[it] + koff_);                    \
        asm volatile("cp.async.commit_group;" ::: "memory");                   \
    } while (0)

    const int rowOffA = (lane & 7) + ((lane >> 3) & 1) * 8;
    const int kOffA   = ((lane >> 4) & 1) * 8;
    const int rowOffB = (lane & 7) + ((lane >> 4) & 1) * 8;
    const int kOffB   = ((lane >> 3) & 1) * 8;

    ISSUE(0);
    if (NK > 1) { ISSUE(1); } else { COMMIT_EMPTY(); }

    for (int kt = 0; kt < NK; kt++) {
        asm volatile("cp.async.wait_group 1;" ::: "memory");
        __syncthreads();
        if (kt + 2 < NK) { ISSUE(kt + 2); } else { COMMIT_EMPTY(); }

        const uint32_t base = sb + (kt % NSTAGE) * STAGE;
#pragma unroll
        for (int ks = 0; ks < 2; ks++) {
            uint32_t a_f[4][4], b_f[4][2];
#pragma unroll
            for (int mt = 0; mt < 4; mt++) {
                uint32_t ad = base + (wm * 64 + mt * 16 + rowOffA) * RPITCH
                            + (ks * 16 + kOffA) * 2;
                LDSM4(a_f[mt], ad);
            }
#pragma unroll
            for (int pr = 0; pr < 2; pr++) {
                uint32_t bd = base + PLANE
                            + (wn * 32 + pr * 16 + rowOffB) * RPITCH
                            + (ks * 16 + kOffB) * 2;
                uint32_t r4[4];
                LDSM4(r4, bd);
                b_f[pr * 2][0] = r4[0];     b_f[pr * 2][1] = r4[1];
                b_f[pr * 2 + 1][0] = r4[2]; b_f[pr * 2 + 1][1] = r4[3];
            }
#pragma unroll
            for (int mt = 0; mt < 4; mt++)
#pragma unroll
                for (int nt = 0; nt < 4; nt++)
                    MMA(acc[mt][nt], a_f[mt], b_f[nt]);
        }
        __syncthreads();
    }

    // epilogue
    const int rq = lane >> 2;
    const int cq = (lane & 3) * 2;
#pragma unroll
    for (int mt = 0; mt < 4; mt++)
#pragma unroll
        for (int nt = 0; nt < 4; nt++) {
            const int row = m0 + wm * 64 + mt * 16 + rq;
            const int col = n0 + wn * 32 + nt * 8 + cq;
            float b0 = bias ? bias[col] : 0.f;
            float b1 = bias ? bias[col + 1] : 0.f;
#pragma unroll
            for (int half = 0; half < 2; half++) {
                const long long rr = (long long)(row + half * 8) * ldc + col + coff;
                float v0 = acc[mt][nt][half * 2 + 0] + b0;
                float v1 = acc[mt][nt][half * 2 + 1] + b1;
                if (doRelu) { v0 = fmaxf(v0, 0.f); v1 = fmaxf(v1, 0.f); }
                if (Cf) {
                    *reinterpret_cast<float2*>(Cf + rr) = make_float2(v0, v1);
                } else {
                    __half2 hp;
                    hp.x = __float2half_rn(v0);
                    hp.y = __float2half_rn(v1);
                    *reinterpret_cast<__half2*>(Ch + rr) = hp;
                }
            }
        }
}

// fp32 -> fp16 rounding (vectorized)
__global__ void to_half_kernel(const float4* __restrict__ in,
                               __half* __restrict__ out, int n4)
{
    for (long long i = blockIdx.x * blockDim.x + threadIdx.x; i < n4;
         i += (long long)gridDim.x * blockDim.x) {
        float4 v = in[i];
        __half2 a, b;
        a.x = __float2half_rn(v.x); a.y = __float2half_rn(v.y);
        b.x = __float2half_rn(v.z); b.y = __float2half_rn(v.w);
        reinterpret_cast<__half2*>(out)[2 * i]     = a;
        reinterpret_cast<__half2*>(out)[2 * i + 1] = b;
    }
}

__global__ void avg_softmax_kernel(const __half* __restrict__ xh,
                                   const float* __restrict__ embed,
                                   float* __restrict__ ew)
{
    __shared__ float avg_s[DD];
    __shared__ float lg[EE_N];

    const int g = blockIdx.x;
    const int d = threadIdx.x;
    const int b = g >> 7;
    const int n = (g >> 3) & 15;
    const int h = g & 7;

    const long long base = (long long)(b * SS_ + n * SEGLEN) * HID + h * DD + d;
    float s = 0.f;
#pragma unroll 8
    for (int l = 0; l < SEGLEN; l++)
        s += __half2float(xh[base + (long long)l * HID]);
    avg_s[d] = s * (1.f / (float)SEGLEN);
    __syncthreads();

    if (d < EE_N) {
        float a = 0.f;
        for (int dd = 0; dd < DD; dd++) a += avg_s[dd] * embed[dd * EE_N + d];
        lg[d] = a;
    }
    __syncthreads();

    if (d == 0) {
        float mx = lg[0];
        for (int e = 1; e < EE_N; e++) mx = fmaxf(mx, lg[e]);
        float ex[EE_N], ssum = 0.f;
        for (int e = 0; e < EE_N; e++) { ex[e] = expf(lg[e] - mx); ssum += ex[e]; }
        float inv = 1.f / ssum;
        for (int e = 0; e < EE_N; e++) ew[g * EE_N + e] = ex[e] * inv;
    }
}

__global__ void mix_kernel(const float* __restrict__ ew,
                           const float* __restrict__ fl1,
                           const float* __restrict__ fl2,
                           __half* __restrict__ m1, __half* __restrict__ m2)
{
    __shared__ float w_s[NGROUP * EE_N];
    const int t = threadIdx.x;
    const float* src = blockIdx.y ? fl2 : fl1;
    __half* dst = blockIdx.y ? m2 : m1;
    const long long p = (long long)blockIdx.x * 128 + t;

    for (int idx = t; idx < NGROUP * EE_N; idx += 128) {
        int g = idx >> 4;
        int n = (g >> 3) & 15;
        int gs = (n > 0) ? (g - HEADS) : g;
        w_s[idx] = ew[gs * EE_N + (idx & 15)];
    }
    float flr[EE_N];
#pragma unroll
    for (int e = 0; e < EE_N; e++) flr[e] = src[(long long)e * (II * DD) + p];
    __syncthreads();

    for (int g = 0; g < NGROUP; g++) {
        float acc = 0.f;
#pragma unroll
        for (int e = 0; e < EE_N; e++) acc = fmaf(w_s[g * EE_N + e], flr[e], acc);
        dst[(long long)g * (II * DD) + p] = __float2half_rn(acc);
    }
}

extern "C" void kernel_launch(void* const* d_in, const int* in_sizes, int n_in,
                              void* d_out, int out_size)
{
    const float* x       = (const float*)d_in[0];
    const float* W_mh    = (const float*)d_in[1];
    const float* b_mh    = (const float*)d_in[2];
    const float* W_merge = (const float*)d_in[3];
    const float* b_merge = (const float*)d_in[4];
    const float* embed   = (const float*)d_in[5];
    const float* fl1     = (const float*)d_in[6];
    const float* fl2     = (const float*)d_in[7];
    float* out = (float*)d_out;

    __half *xb, *wmh, *wmg, *xh, *m1, *m2, *hh, *y2;
    float* ew;
    cudaGetSymbolAddress((void**)&xb, g_xb);
    cudaGetSymbolAddress((void**)&wmh, g_wmh);
    cudaGetSymbolAddress((void**)&wmg, g_wmg);
    cudaGetSymbolAddress((void**)&xh, g_xh);
    cudaGetSymbolAddress((void**)&m1, g_m1);
    cudaGetSymbolAddress((void**)&m2, g_m2);
    cudaGetSymbolAddress((void**)&hh, g_h);
    cudaGetSymbolAddress((void**)&y2, g_y2);
    cudaGetSymbolAddress((void**)&ew, g_ew);

    cudaFuncSetAttribute(mma_gemm, cudaFuncAttributeMaxDynamicSharedMemorySize, SMEM_BYTES);

    // 0) round fp32 inputs to fp16
    to_half_kernel<<<2048, 256>>>((const float4*)x, xb, MROWS * HID / 4);
    to_half_kernel<<<256, 256>>>((const float4*)W_mh, wmh, HID * HID / 4);
    to_half_kernel<<<256, 256>>>((const float4*)W_merge, wmg, HID * HID / 4);

    // 1) xh = x @ W_mh^T + b_mh  (fp16 out)
    mma_gemm<<<dim3(HID / 128, MROWS / 128, 1), 256, SMEM_BYTES>>>(
        xb, wmh, xh, nullptr, b_mh,
        HID, HID, HID, HID, 0, 0, 0, 0);

    // 2) routing softmax
    avg_softmax_kernel<<<NGROUP, DD>>>(xh, embed, ew);

    // 3) causally-shifted expert mixing (fp16 out)
    mix_kernel<<<dim3(II * DD / 128, 2), 128>>>(ew, fl1, fl2, m1, m2);

    // 4) h = relu(X @ m1^T)  batched 512x: M=256,N=512,K=128
    mma_gemm<<<dim3(II / 128, SEGLEN / 128, NGROUP), 256, SMEM_BYTES>>>(
        xh, m1, hh, nullptr, nullptr,
        DD, DD, DD, II,
        (long long)SEGLEN * DD, (long long)II * DD, (long long)SEGLEN * II, 1);

    // 5) y2 = h @ m2^T  batched 512x: M=256,N=128,K=512
    mma_gemm<<<dim3(DD / 128, SEGLEN / 128, NGROUP), 256, SMEM_BYTES>>>(
        hh, m2, y2, nullptr, nullptr,
        II, II, II, DD,
        (long long)SEGLEN * II, (long long)DD * II, (long long)SEGLEN * DD, 0);

    // 6) out = y2 @ W_merge^T + b_merge  (fp32 out)
    mma_gemm<<<dim3(HID / 128, MROWS / 128, 1), 256, SMEM_BYTES>>>(
        y2, wmg, nullptr, out, b_merge,
        HID, HID, HID, HID, 0, 0, 0, 0);
}

// round 10
// speedup vs baseline: 2.4280x; 1.0991x over previous
#include <cuda_runtime.h>
#include <cuda_fp16.h>
#include <cstdint>

#define HID 1024
#define HEADS 8
#define DD 128
#define NSEG 16
#define SEGLEN 256
#define EE_N 16
#define II 512
#define NGROUP 512
#define MROWS 16384
#define SS_ 4096

__device__ __half g_xb[MROWS * HID];
__device__ __half g_wmh[HID * HID];
__device__ __half g_wmg[HID * HID];
__device__ __half g_xh[MROWS * HID];
__device__ float  g_ew[NGROUP * EE_N];
__device__ __half g_m1[NGROUP * II * DD];
__device__ __half g_m2[NGROUP * DD * II];
__device__ __half g_h[NGROUP * SEGLEN * II];
__device__ __half g_y2[MROWS * HID];

__device__ __forceinline__ uint32_t smem_u32(const void* p) {
    uint32_t a;
    asm("{ .reg .u64 t; cvta.to.shared.u64 t, %1; cvt.u32.u64 %0, t; }" : "=r"(a) : "l"(p));
    return a;
}
__device__ __forceinline__ void cp_async16(uint32_t dst, const void* src) {
    asm volatile("cp.async.cg.shared.global [%0], [%1], 16;" :: "r"(dst), "l"(src) : "memory");
}

#define LDSM4(r, ad) \
    asm volatile("ldmatrix.sync.aligned.m8n8.x4.shared.b16 {%0,%1,%2,%3}, [%4];" \
        : "=r"((r)[0]), "=r"((r)[1]), "=r"((r)[2]), "=r"((r)[3]) : "r"(ad))

#define MMA(c, a, b) \
    asm volatile("mma.sync.aligned.m16n8k16.row.col.f32.f16.f16.f32 " \
        "{%0,%1,%2,%3},{%4,%5,%6,%7},{%8,%9},{%0,%1,%2,%3};" \
        : "+f"((c)[0]), "+f"((c)[1]), "+f"((c)[2]), "+f"((c)[3]) \
        : "r"((a)[0]), "r"((a)[1]), "r"((a)[2]), "r"((a)[3]), "r"((b)[0]), "r"((b)[1]))

// K-chunk 64 (128B rows), pitch 144: (9r)%8 = r%8 -> 8 consecutive rows
// hit 8 distinct 16B slots mod 128B => conflict-free ldmatrix.
#define RPITCH 144
#define PLANE  (128 * RPITCH)          // 18432
#define STAGE  (2 * PLANE)             // 36864 (A plane + B plane)
#define SMEM_BYTES (2 * STAGE)         // 73728 -> 2 CTAs/SM (<= ~95KB/CTA)

// C[128,128] += A * B^T over K; fp16 operands; fp32 accum.
// 8 warps, warp tile 64x32. K % 64 == 0.
__global__ __launch_bounds__(256)
void mma_gemm(const __half* __restrict__ A, const __half* __restrict__ B,
              __half* __restrict__ Ch, float* __restrict__ Cf,
              const float* __restrict__ bias,
              int K, int lda, int ldb, int ldc,
              long long aB, long long bB, long long cB, int doRelu)
{
    extern __shared__ char dsm[];
    const int tid  = threadIdx.x;
    const int lane = tid & 31;
    const int warp = tid >> 5;
    const int wm   = warp & 1;        // 0..1 : 64-row slab
    const int wn   = warp >> 1;       // 0..3 : 32-col slab

    const long long gz = blockIdx.z;
    A += gz * aB;
    B += gz * bB;
    const long long coff = gz * cB;
    const int m0 = blockIdx.y * 128;
    const int n0 = blockIdx.x * 128;

    const uint32_t sb = smem_u32(dsm);
    const int NK = K >> 6;

    float acc[4][4][4];
#pragma unroll
    for (int i = 0; i < 4; i++)
#pragma unroll
        for (int j = 0; j < 4; j++)
#pragma unroll
            for (int q = 0; q < 4; q++) acc[i][j][q] = 0.f;

    // cp.async: 2 planes x 128 rows x 8 chunks(16B) = 2048 chunks; 8 per thread
    const __half* srcP[8];
    uint32_t dstOff[8];
#pragma unroll
    for (int it = 0; it < 8; it++) {
        int idx = it * 256 + tid;
        int pl = idx >> 10;            // 0=A, 1=B
        int r  = (idx >> 3) & 127;
        int ch = idx & 7;
        srcP[it] = (pl ? B + (long long)(n0 + r) * ldb
                       : A + (long long)(m0 + r) * lda) + ch * 8;
        dstOff[it] = pl * PLANE + r * RPITCH + ch * 16;
    }

#define ISSUE(kt)                                                              \
    do {                                                                       \
        const int koff_ = (kt) << 6;                                           \
        const uint32_t db_ = sb + ((kt) & 1) * STAGE;                          \
        _Pragma("unroll")                                                      \
        for (int it = 0; it < 8; it++)                                         \
            cp_async16(db_ + dstOff[it], srcP[it] + koff_);                    \
        asm volatile("cp.async.commit_group;" ::: "memory");                   \
    } while (0)

    const int rowOffA = (lane & 7) + ((lane >> 3) & 1) * 8;
    const int kOffA   = ((lane >> 4) & 1) * 8;
    const int rowOffB = (lane & 7) + ((lane >> 4) & 1) * 8;
    const int kOffB   = ((lane >> 3) & 1) * 8;

    ISSUE(0);
    for (int kt = 0; kt < NK; kt++) {
        if (kt + 1 < NK) {
            ISSUE(kt + 1);
            asm volatile("cp.async.wait_group 1;" ::: "memory");
        } else {
            asm volatile("cp.async.wait_group 0;" ::: "memory");
        }
        __syncthreads();

        const uint32_t base = sb + (kt & 1) * STAGE;
#pragma unroll
        for (int ks = 0; ks < 4; ks++) {
            uint32_t a_f[4][4], b_f[4][2];
#pragma unroll
            for (int mt = 0; mt < 4; mt++) {
                uint32_t ad = base + (wm * 64 + mt * 16 + rowOffA) * RPITCH
                            + (ks * 16 + kOffA) * 2;
                LDSM4(a_f[mt], ad);
            }
#pragma unroll
            for (int pr = 0; pr < 2; pr++) {
                uint32_t bd = base + PLANE
                            + (wn * 32 + pr * 16 + rowOffB) * RPITCH
                            + (ks * 16 + kOffB) * 2;
                uint32_t r4[4];
                LDSM4(r4, bd);
                b_f[pr * 2][0] = r4[0];     b_f[pr * 2][1] = r4[1];
                b_f[pr * 2 + 1][0] = r4[2]; b_f[pr * 2 + 1][1] = r4[3];
            }
#pragma unroll
            for (int mt = 0; mt < 4; mt++)
#pragma unroll
                for (int nt = 0; nt < 4; nt++)
                    MMA(acc[mt][nt], a_f[mt], b_f[nt]);
        }
        __syncthreads();
    }

    // epilogue
    const int rq = lane >> 2;
    const int cq = (lane & 3) * 2;
#pragma unroll
    for (int mt = 0; mt < 4; mt++)
#pragma unroll
        for (int nt = 0; nt < 4; nt++) {
            const int row = m0 + wm * 64 + mt * 16 + rq;
            const int col = n0 + wn * 32 + nt * 8 + cq;
            float b0 = bias ? bias[col] : 0.f;
            float b1 = bias ? bias[col + 1] : 0.f;
#pragma unroll
            for (int half = 0; half < 2; half++) {
                const long long rr = (long long)(row + half * 8) * ldc + col + coff;
                float v0 = acc[mt][nt][half * 2 + 0] + b0;
                float v1 = acc[mt][nt][half * 2 + 1] + b1;
                if (doRelu) { v0 = fmaxf(v0, 0.f); v1 = fmaxf(v1, 0.f); }
                if (Cf) {
                    *reinterpret_cast<float2*>(Cf + rr) = make_float2(v0, v1);
                } else {
                    __half2 hp;
                    hp.x = __float2half_rn(v0);
                    hp.y = __float2half_rn(v1);
                    *reinterpret_cast<__half2*>(Ch + rr) = hp;
                }
            }
        }
}

// fp32 -> fp16 rounding (vectorized)
__global__ void to_half_kernel(const float4* __restrict__ in,
                               __half* __restrict__ out, int n4)
{
    for (long long i = blockIdx.x * blockDim.x + threadIdx.x; i < n4;
         i += (long long)gridDim.x * blockDim.x) {
        float4 v = in[i];
        __half2 a, b;
        a.x = __float2half_rn(v.x); a.y = __float2half_rn(v.y);
        b.x = __float2half_rn(v.z); b.y = __float2half_rn(v.w);
        reinterpret_cast<__half2*>(out)[2 * i]     = a;
        reinterpret_cast<__half2*>(out)[2 * i + 1] = b;
    }
}

__global__ void avg_softmax_kernel(const __half* __restrict__ xh,
                                   const float* __restrict__ embed,
                                   float* __restrict__ ew)
{
    __shared__ float avg_s[DD];
    __shared__ float lg[EE_N];

    const int g = blockIdx.x;
    const int d = threadIdx.x;
    const int b = g >> 7;
    const int n = (g >> 3) & 15;
    const int h = g & 7;

    const long long base = (long long)(b * SS_ + n * SEGLEN) * HID + h * DD + d;
    float s = 0.f;
#pragma unroll 8
    for (int l = 0; l < SEGLEN; l++)
        s += __half2float(xh[base + (long long)l * HID]);
    avg_s[d] = s * (1.f / (float)SEGLEN);
    __syncthreads();

    if (d < EE_N) {
        float a = 0.f;
        for (int dd = 0; dd < DD; dd++) a += avg_s[dd] * embed[dd * EE_N + d];
        lg[d] = a;
    }
    __syncthreads();

    if (d == 0) {
        float mx = lg[0];
        for (int e = 1; e < EE_N; e++) mx = fmaxf(mx, lg[e]);
        float ex[EE_N], ssum = 0.f;
        for (int e = 0; e < EE_N; e++) { ex[e] = expf(lg[e] - mx); ssum += ex[e]; }
        float inv = 1.f / ssum;
        for (int e = 0; e < EE_N; e++) ew[g * EE_N + e] = ex[e] * inv;
    }
}

__global__ void mix_kernel(const float* __restrict__ ew,
                           const float* __restrict__ fl1,
                           const float* __restrict__ fl2,
                           __half* __restrict__ m1, __half* __restrict__ m2)
{
    __shared__ float w_s[NGROUP * EE_N];
    const int t = threadIdx.x;
    const float* src = blockIdx.y ? fl2 : fl1;
    __half* dst = blockIdx.y ? m2 : m1;
    const long long p = (long long)blockIdx.x * 128 + t;

    for (int idx = t; idx < NGROUP * EE_N; idx += 128) {
        int g = idx >> 4;
        int n = (g >> 3) & 15;
        int gs = (n > 0) ? (g - HEADS) : g;
        w_s[idx] = ew[gs * EE_N + (idx & 15)];
    }
    float flr[EE_N];
#pragma unroll
    for (int e = 0; e < EE_N; e++) flr[e] = src[(long long)e * (II * DD) + p];
    __syncthreads();

    for (int g = 0; g < NGROUP; g++) {
        float acc = 0.f;
#pragma unroll
        for (int e = 0; e < EE_N; e++) acc = fmaf(w_s[g * EE_N + e], flr[e], acc);
        dst[(long long)g * (II * DD) + p] = __float2half_rn(acc);
    }
}

extern "C" void kernel_launch(void* const* d_in, const int* in_sizes, int n_in,
                              void* d_out, int out_size)
{
    const float* x       = (const float*)d_in[0];
    const float* W_mh    = (const float*)d_in[1];
    const float* b_mh    = (const float*)d_in[2];
    const float* W_merge = (const float*)d_in[3];
    const float* b_merge = (const float*)d_in[4];
    const float* embed   = (const float*)d_in[5];
    const float* fl1     = (const float*)d_in[6];
    const float* fl2     = (const float*)d_in[7];
    float* out = (float*)d_out;

    __half *xb, *wmh, *wmg, *xh, *m1, *m2, *hh, *y2;
    float* ew;
    cudaGetSymbolAddress((void**)&xb, g_xb);
    cudaGetSymbolAddress((void**)&wmh, g_wmh);
    cudaGetSymbolAddress((void**)&wmg, g_wmg);
    cudaGetSymbolAddress((void**)&xh, g_xh);
    cudaGetSymbolAddress((void**)&m1, g_m1);
    cudaGetSymbolAddress((void**)&m2, g_m2);
    cudaGetSymbolAddress((void**)&hh, g_h);
    cudaGetSymbolAddress((void**)&y2, g_y2);
    cudaGetSymbolAddress((void**)&ew, g_ew);

    cudaFuncSetAttribute(mma_gemm, cudaFuncAttributeMaxDynamicSharedMemorySize, SMEM_BYTES);

    // 0) round fp32 inputs to fp16
    to_half_kernel<<<2048, 256>>>((const float4*)x, xb, MROWS * HID / 4);
    to_half_kernel<<<256, 256>>>((const float4*)W_mh, wmh, HID * HID / 4);
    to_half_kernel<<<256, 256>>>((const float4*)W_merge, wmg, HID * HID / 4);

    // 1) xh = x @ W_mh^T + b_mh  (fp16 out)
    mma_gemm<<<dim3(HID / 128, MROWS / 128, 1), 256, SMEM_BYTES>>>(
        xb, wmh, xh, nullptr, b_mh,
        HID, HID, HID, HID, 0, 0, 0, 0);

    // 2) routing softmax
    avg_softmax_kernel<<<NGROUP, DD>>>(xh, embed, ew);

    // 3) causally-shifted expert mixing (fp16 out)
    mix_kernel<<<dim3(II * DD / 128, 2), 128>>>(ew, fl1, fl2, m1, m2);

    // 4) h = relu(X @ m1^T)  batched 512x: M=256,N=512,K=128
    mma_gemm<<<dim3(II / 128, SEGLEN / 128, NGROUP), 256, SMEM_BYTES>>>(
        xh, m1, hh, nullptr, nullptr,
        DD, DD, DD, II,
        (long long)SEGLEN * DD, (long long)II * DD, (long long)SEGLEN * II, 1);

    // 5) y2 = h @ m2^T  batched 512x: M=256,N=128,K=512
    mma_gemm<<<dim3(DD / 128, SEGLEN / 128, NGROUP), 256, SMEM_BYTES>>>(
        hh, m2, y2, nullptr, nullptr,
        II, II, II, DD,
        (long long)SEGLEN * II, (long long)DD * II, (long long)SEGLEN * DD, 0);

    // 6) out = y2 @ W_merge^T + b_merge  (fp32 out)
    mma_gemm<<<dim3(HID / 128, MROWS / 128, 1), 256, SMEM_BYTES>>>(
        y2, wmg, nullptr, out, b_merge,
        HID, HID, HID, HID, 0, 0, 0, 0);
}